// round 14
// baseline (speedup 1.0000x reference)
#include <cuda_runtime.h>
#include <cuda_bf16.h>

// Grouped 1x7 conv (NCHW, groups=2, shared weights) + roll(H), tensor cores
// (m16n8k16 BF16, 3xBF16 split: hh + hl + lh, fp32 accumulate).
//
// Single kernel. Each block splits its OWN 48-oc weight half into smem
// (4608 uint2, 12 items/thread, L2-resident w) overlapped with x staging.
// K reordered as k = ic*8 + kw' (kw' 0..7, kw'=7 zero) -> bf16x2 pairs are
// adjacent kw -> B pairs = adjacent pixels, K' = 192 = 12 k16-chunks.
// Block = (h, g, m-half): 48 oc x 56 px, 384 thr, 2 CTA/SM, 224 blocks.

#define Hdim 56
#define Wdim 56
#define HW   3136
#define ICg  24

#define SWP  100   // u64 stride per oc row (96 used)
#define SXP  64    // u64 stride per ic row of x pairs

#define W_TILE_BYTES (48 * SWP * 8)              // 38400
#define SX_BYTES     (ICg * SXP * 8)             // 12288

__device__ __forceinline__ unsigned bf16bits(float v) {
    return (unsigned)__bfloat16_as_ushort(__float2bfloat16_rn(v));
}

__device__ __forceinline__ uint2 split_pack(float v0, float v1) {
    unsigned h0 = bf16bits(v0);
    unsigned h1 = bf16bits(v1);
    float r0 = v0 - __bfloat162float(__ushort_as_bfloat16((unsigned short)h0));
    float r1 = v1 - __bfloat162float(__ushort_as_bfloat16((unsigned short)h1));
    unsigned l0 = bf16bits(r0);
    unsigned l1 = bf16bits(r1);
    return make_uint2(h0 | (h1 << 16), l0 | (l1 << 16));
}

__device__ __forceinline__ void mma_bf16(float c[4],
                                         unsigned a0, unsigned a1,
                                         unsigned a2, unsigned a3,
                                         unsigned b0, unsigned b1) {
    asm volatile(
        "mma.sync.aligned.m16n8k16.row.col.f32.bf16.bf16.f32 "
        "{%0,%1,%2,%3},{%4,%5,%6,%7},{%8,%9},{%0,%1,%2,%3};"
        : "+f"(c[0]), "+f"(c[1]), "+f"(c[2]), "+f"(c[3])
        : "r"(a0), "r"(a1), "r"(a2), "r"(a3), "r"(b0), "r"(b1));
}

__global__ __launch_bounds__(384, 2)
void conv1x7_bf2(const float* __restrict__ x, const float* __restrict__ w,
                 const int* __restrict__ shift, float* __restrict__ out)
{
    extern __shared__ char smem[];
    uint2* swq = (uint2*)smem;                       // [48][SWP]
    uint2* sxp = (uint2*)(smem + W_TILE_BYTES);      // [24][SXP]

    const int tid = threadIdx.x;
    const int h   = blockIdx.x;
    const int g   = blockIdx.y;
    const int mh  = blockIdx.z;      // oc in [mh*48, mh*48+48)

    // ---- split this block's 48-oc weight half into smem ----
    // swq[oc_l][j], j = ic*4 + t : pack(w[ic][oc][2t], w[ic][oc][2t+1]) (t=3: hi=w6, lo=0)
    const float* wg = w + (size_t)mh * 48 * 7;
    #pragma unroll
    for (int it = 0; it < 12; it++) {                // 12*384 = 4608
        int i    = it * 384 + tid;
        int oc_l = i / 96;
        int j    = i - oc_l * 96;
        int ic   = j >> 2;
        int t    = j & 3;
        const float* wp = wg + ic * 672 + oc_l * 7;
        float v0 = wp[2 * t];
        float v1 = (t < 3) ? wp[2 * t + 1] : 0.f;
        swq[oc_l * SWP + j] = split_pack(v0, v1);
    }

    // ---- stage x row as split sliding-window pairs ----
    const float* xrow = x + (size_t)g * (ICg * HW) + h * Wdim;
    #pragma unroll
    for (int it = 0; it < 4; it++) {                 // 4*384 = 1536
        int i  = it * 384 + tid;
        int ic = i >> 6;
        int p  = i & 63;
        int w0 = p - 3, w1 = p - 2;
        float v0 = (w0 >= 0 && w0 < Wdim) ? xrow[ic * HW + w0] : 0.f;
        float v1 = (w1 >= 0 && w1 < Wdim) ? xrow[ic * HW + w1] : 0.f;
        sxp[ic * SXP + p] = split_pack(v0, v1);
    }
    __syncthreads();

    const int wid  = tid >> 5;        // 0..11
    const int mt   = wid >> 2;        // m-tile 0..2
    const int nq   = wid & 3;         // 0..3
    const int nf   = (nq == 3) ? 1 : 2;
    const int nt0  = nq * 2;          // frags nt0..nt0+nf-1 (7 total)
    const int lane = tid & 31;
    const int lg   = lane >> 2;       // 0..7
    const int lk   = lane & 3;        // 0..3

    const uint2* A0p = swq + (mt * 16 + lg) * SWP + lk;   // row lg
    const uint2* A1p = A0p + 8 * SWP;                     // row lg+8
    const int pb0 = nt0 * 8 + lg + 2 * lk;                // B pixel index

    float c[2][4];
    #pragma unroll
    for (int f = 0; f < 2; f++)
        #pragma unroll
        for (int q = 0; q < 4; q++) c[f][q] = 0.f;

    #pragma unroll
    for (int ks = 0; ks < 12; ks++) {
        const int j = ks * 8;
        uint2 qa0 = A0p[j];                   // (hi,lo) row lg,  k 2lk
        uint2 qa1 = A1p[j];                   // row lg+8
        uint2 qa2 = A0p[j + 4];               // k+8
        uint2 qa3 = A1p[j + 4];

        const uint2* b0p = sxp + (2 * ks) * SXP;       // ic = 2ks
        const uint2* b1p = b0p + SXP;                  // ic = 2ks+1

        uint2 B0[2], B1[2];
        #pragma unroll
        for (int f = 0; f < 2; f++) {
            if (f < nf) {
                B0[f] = b0p[pb0 + f * 8];
                B1[f] = b1p[pb0 + f * 8];
            }
        }

        // hh
        #pragma unroll
        for (int f = 0; f < 2; f++)
            if (f < nf)
                mma_bf16(c[f], qa0.x, qa1.x, qa2.x, qa3.x, B0[f].x, B1[f].x);
        // hl
        #pragma unroll
        for (int f = 0; f < 2; f++)
            if (f < nf)
                mma_bf16(c[f], qa0.x, qa1.x, qa2.x, qa3.x, B0[f].y, B1[f].y);
        // lh
        #pragma unroll
        for (int f = 0; f < 2; f++)
            if (f < nf)
                mma_bf16(c[f], qa0.y, qa1.y, qa2.y, qa3.y, B0[f].x, B1[f].x);
    }

    // ---- roll + store ----
    const int s = *shift;
    int ho = (h + s) % Hdim;
    if (ho < 0) ho += Hdim;

    float* ob = out + (size_t)(g * 96 + mh * 48 + mt * 16 + lg) * HW
                    + ho * Wdim + (nt0 * 8 + 2 * lk);
    #pragma unroll
    for (int f = 0; f < 2; f++) {
        if (f < nf) {
            *(float2*)(ob + f * 8)          = make_float2(c[f][0], c[f][1]);
            *(float2*)(ob + 8 * HW + f * 8) = make_float2(c[f][2], c[f][3]);
        }
    }
}

extern "C" void kernel_launch(void* const* d_in, const int* in_sizes, int n_in,
                              void* d_out, int out_size)
{
    const float* x     = (const float*)d_in[0];
    const float* w     = (const float*)d_in[1];
    const int*   shift = (const int*)  d_in[2];
    float*       out   = (float*)d_out;

    const int smem_bytes = W_TILE_BYTES + SX_BYTES;   // 50688
    cudaFuncSetAttribute(conv1x7_bf2,
                         cudaFuncAttributeMaxDynamicSharedMemorySize, smem_bytes);

    dim3 grid(Hdim, 2, 2);   // 56 x 2 x 2 = 224 blocks
    conv1x7_bf2<<<grid, 384, smem_bytes>>>(x, w, shift, out);
}

// round 15
// speedup vs baseline: 1.1274x; 1.1274x over previous
#include <cuda_runtime.h>
#include <cuda_bf16.h>

// Grouped 1x7 conv (NCHW, groups=2, shared weights) + roll(H), tensor cores
// (m16n8k16 BF16, 3xBF16 split: hh + hl + lh, fp32 accumulate).
//
// Single kernel, single launch. Per block:
//   1. COALESCED uint4 copy of its raw 48-oc weight half into padded smem.
//   2. Split raw smem -> (bf16_hi, bf16_lo) packed tile (LDS source).
//   3. Stage x row as split sliding-window pairs (overlapped).
// K = ic*8 + kw' (kw' 7 zero) -> B pairs = adjacent pixels, 12 k16-chunks.
// Block = (h, g, m-half): 48 oc x 56 px, 384 thr, 2 CTA/SM, 224 blocks.

#define Hdim 56
#define Wdim 56
#define HW   3136
#define ICg  24

#define SWP  100   // u64 stride per oc row of split tile (96 used)
#define SXP  64    // u64 stride per ic row of x pairs
#define RWS  340   // float stride per ic row of raw w half (336 used; %4==0, %32==20)

#define W_TILE_BYTES (48 * SWP * 8)              // 38400
#define SX_BYTES     (ICg * SXP * 8)             // 12288
#define RAW_BYTES    (ICg * RWS * 4)             // 32640
#define RAW_OFF      (W_TILE_BYTES + SX_BYTES)   // 50688

__device__ __forceinline__ unsigned bf16bits(float v) {
    return (unsigned)__bfloat16_as_ushort(__float2bfloat16_rn(v));
}

__device__ __forceinline__ uint2 split_pack(float v0, float v1) {
    unsigned h0 = bf16bits(v0);
    unsigned h1 = bf16bits(v1);
    float r0 = v0 - __bfloat162float(__ushort_as_bfloat16((unsigned short)h0));
    float r1 = v1 - __bfloat162float(__ushort_as_bfloat16((unsigned short)h1));
    unsigned l0 = bf16bits(r0);
    unsigned l1 = bf16bits(r1);
    return make_uint2(h0 | (h1 << 16), l0 | (l1 << 16));
}

__device__ __forceinline__ void mma_bf16(float c[4],
                                         unsigned a0, unsigned a1,
                                         unsigned a2, unsigned a3,
                                         unsigned b0, unsigned b1) {
    asm volatile(
        "mma.sync.aligned.m16n8k16.row.col.f32.bf16.bf16.f32 "
        "{%0,%1,%2,%3},{%4,%5,%6,%7},{%8,%9},{%0,%1,%2,%3};"
        : "+f"(c[0]), "+f"(c[1]), "+f"(c[2]), "+f"(c[3])
        : "r"(a0), "r"(a1), "r"(a2), "r"(a3), "r"(b0), "r"(b1));
}

__global__ __launch_bounds__(384, 2)
void conv1x7_bf3(const float* __restrict__ x, const float* __restrict__ w,
                 const int* __restrict__ shift, float* __restrict__ out)
{
    extern __shared__ char smem[];
    uint2* swq = (uint2*)smem;                       // [48][SWP] split tile
    uint2* sxp = (uint2*)(smem + W_TILE_BYTES);      // [24][SXP] x pairs
    float* raw = (float*)(smem + RAW_OFF);           // [24][RWS] raw w half

    const int tid = threadIdx.x;
    const int h   = blockIdx.x;
    const int g   = blockIdx.y;
    const int mh  = blockIdx.z;      // oc in [mh*48, mh*48+48)

    // ---- 1. coalesced copy of raw weight half: 24 chunks of 336 floats ----
    // chunk ic lives at w + ic*672 + mh*336 (16B aligned), 84 uint4 each.
    {
        const float* wg = w + mh * 336;
        for (int iq = tid; iq < ICg * 84; iq += 384) {   // 2016 uint4
            int ic = iq / 84;
            int rq = iq - ic * 84;
            uint4 v = *(const uint4*)(wg + ic * 672 + rq * 4);
            *(uint4*)(raw + ic * RWS + rq * 4) = v;
        }
    }

    // ---- 2. stage x row as split sliding-window pairs (independent) ----
    const float* xrow = x + (size_t)g * (ICg * HW) + h * Wdim;
    #pragma unroll
    for (int it = 0; it < 4; it++) {                 // 4*384 = 1536
        int i  = it * 384 + tid;
        int ic = i >> 6;
        int p  = i & 63;
        int w0 = p - 3, w1 = p - 2;
        float v0 = (w0 >= 0 && w0 < Wdim) ? xrow[ic * HW + w0] : 0.f;
        float v1 = (w1 >= 0 && w1 < Wdim) ? xrow[ic * HW + w1] : 0.f;
        sxp[ic * SXP + p] = split_pack(v0, v1);
    }
    __syncthreads();

    // ---- 3. split raw smem -> packed tile: swq[oc_l][ic*4+t] ----
    #pragma unroll
    for (int it = 0; it < 12; it++) {                // 12*384 = 4608
        int i    = it * 384 + tid;
        int oc_l = i / 96;
        int j    = i - oc_l * 96;
        int ic   = j >> 2;
        int t    = j & 3;
        const float* rp = raw + ic * RWS + oc_l * 7;
        float v0 = rp[2 * t];
        float v1 = (t < 3) ? rp[2 * t + 1] : 0.f;
        swq[oc_l * SWP + j] = split_pack(v0, v1);
    }
    __syncthreads();

    const int wid  = tid >> 5;        // 0..11
    const int mt   = wid >> 2;        // m-tile 0..2
    const int nq   = wid & 3;         // 0..3
    const int nf   = (nq == 3) ? 1 : 2;
    const int nt0  = nq * 2;          // frags nt0..nt0+nf-1 (7 total)
    const int lane = tid & 31;
    const int lg   = lane >> 2;       // 0..7
    const int lk   = lane & 3;        // 0..3

    const uint2* A0p = swq + (mt * 16 + lg) * SWP + lk;   // row lg
    const uint2* A1p = A0p + 8 * SWP;                     // row lg+8
    const int pb0 = nt0 * 8 + lg + 2 * lk;                // B pixel index

    float c[2][4];
    #pragma unroll
    for (int f = 0; f < 2; f++)
        #pragma unroll
        for (int q = 0; q < 4; q++) c[f][q] = 0.f;

    #pragma unroll
    for (int ks = 0; ks < 12; ks++) {
        const int j = ks * 8;
        uint2 qa0 = A0p[j];                   // (hi,lo) row lg,  k 2lk
        uint2 qa1 = A1p[j];                   // row lg+8
        uint2 qa2 = A0p[j + 4];               // k+8
        uint2 qa3 = A1p[j + 4];

        const uint2* b0p = sxp + (2 * ks) * SXP;       // ic = 2ks
        const uint2* b1p = b0p + SXP;                  // ic = 2ks+1

        uint2 B0[2], B1[2];
        #pragma unroll
        for (int f = 0; f < 2; f++) {
            if (f < nf) {
                B0[f] = b0p[pb0 + f * 8];
                B1[f] = b1p[pb0 + f * 8];
            }
        }

        // hh
        #pragma unroll
        for (int f = 0; f < 2; f++)
            if (f < nf)
                mma_bf16(c[f], qa0.x, qa1.x, qa2.x, qa3.x, B0[f].x, B1[f].x);
        // hl
        #pragma unroll
        for (int f = 0; f < 2; f++)
            if (f < nf)
                mma_bf16(c[f], qa0.x, qa1.x, qa2.x, qa3.x, B0[f].y, B1[f].y);
        // lh
        #pragma unroll
        for (int f = 0; f < 2; f++)
            if (f < nf)
                mma_bf16(c[f], qa0.y, qa1.y, qa2.y, qa3.y, B0[f].x, B1[f].x);
    }

    // ---- roll + store ----
    const int s = *shift;
    int ho = (h + s) % Hdim;
    if (ho < 0) ho += Hdim;

    float* ob = out + (size_t)(g * 96 + mh * 48 + mt * 16 + lg) * HW
                    + ho * Wdim + (nt0 * 8 + 2 * lk);
    #pragma unroll
    for (int f = 0; f < 2; f++) {
        if (f < nf) {
            *(float2*)(ob + f * 8)          = make_float2(c[f][0], c[f][1]);
            *(float2*)(ob + 8 * HW + f * 8) = make_float2(c[f][2], c[f][3]);
        }
    }
}

extern "C" void kernel_launch(void* const* d_in, const int* in_sizes, int n_in,
                              void* d_out, int out_size)
{
    const float* x     = (const float*)d_in[0];
    const float* w     = (const float*)d_in[1];
    const int*   shift = (const int*)  d_in[2];
    float*       out   = (float*)d_out;

    const int smem_bytes = RAW_OFF + RAW_BYTES;   // 83328
    cudaFuncSetAttribute(conv1x7_bf3,
                         cudaFuncAttributeMaxDynamicSharedMemorySize, smem_bytes);

    dim3 grid(Hdim, 2, 2);   // 56 x 2 x 2 = 224 blocks
    conv1x7_bf3<<<grid, 384, smem_bytes>>>(x, w, shift, out);
}